// round 12
// baseline (speedup 1.0000x reference)
#include <cuda_runtime.h>
#include <math.h>

#define B0 32
#define C0 512
#define HW 4096
#define DC 32
#define NS 16
#define RK 32
#define LL 512

// ---- global scratch (static device arrays; no runtime malloc) ----
__device__ float g_avg[B0 * C0];
__device__ float g_mx[B0 * C0];
__device__ float g_U[B0 * 2 * DC * LL];      // u layout [bk*32+d][l]
__device__ float g_Delta[B0 * 2 * DC * LL];  // post-softplus delta
__device__ float g_Bs[B0 * 2 * LL * NS];     // [bk][l][n]
__device__ float g_Cs[B0 * 2 * LL * NS];     // [bk][l][n]
__device__ float g_yb[B0 * LL];              // atomically accumulated sum_d w*y
__device__ unsigned g_cnt[B0];               // per-b completion counters
__device__ float g_attn[B0 * C0];

__device__ __forceinline__ float gelu_exact(float v) {
    return 0.5f * v * (1.0f + erff(v * 0.70710678118654752f));
}
__device__ __forceinline__ float ex2_fast(float x) {
    float y;
    asm("ex2.approx.ftz.f32 %0, %1;" : "=f"(y) : "f"(x));
    return y;
}
__device__ __forceinline__ float softplus_fast(float a) {
    return fmaxf(a, 0.0f) + __logf(1.0f + __expf(-fabsf(a)));
}

// ============================================================
// K1: avg + max pool.  256 MB read, HBM-bound (~6.7 TB/s measured).
// ============================================================
__global__ void pool_kernel(const float* __restrict__ x) {
    int bc = blockIdx.x;
    const float4* xp = (const float4*)(x + (size_t)bc * HW);
    float s = 0.0f, m = -INFINITY;
#pragma unroll
    for (int it = 0; it < 4; it++) {
        int i = it * 256 + threadIdx.x;
        float4 v = xp[i];
        s += (v.x + v.y) + (v.z + v.w);
        m = fmaxf(m, fmaxf(fmaxf(v.x, v.y), fmaxf(v.z, v.w)));
    }
#pragma unroll
    for (int o = 16; o; o >>= 1) {
        s += __shfl_xor_sync(0xffffffffu, s, o);
        m = fmaxf(m, __shfl_xor_sync(0xffffffffu, m, o));
    }
    __shared__ float ss[8], sm[8];
    int w = threadIdx.x >> 5;
    if ((threadIdx.x & 31) == 0) { ss[w] = s; sm[w] = m; }
    __syncthreads();
    if (threadIdx.x == 0) {
        float S = ss[0], M = sm[0];
#pragma unroll
        for (int i = 1; i < 8; i++) { S += ss[i]; M = fmaxf(M, sm[i]); }
        g_avg[bc] = S * (1.0f / (float)HW);
        g_mx[bc] = M;
    }
}

// ============================================================
// K2: prep v2 (512 blocks x 256 thr); zeroes g_yb and g_cnt.
// ============================================================
__global__ void __launch_bounds__(256)
prep_kernel(const float* __restrict__ xc_w,
            const float* __restrict__ dtc_w,
            const float* __restrict__ dtc_b,
            const float* __restrict__ w_cin,
            const float* __restrict__ bn_g,
            const float* __restrict__ bn_b,
            const float* __restrict__ bn_m,
            const float* __restrict__ bn_v) {
    const int bk = blockIdx.x >> 3;
    const int b = bk >> 1, k = bk & 1;
    const int l0 = (blockIdx.x & 7) << 6;
    const int tid = threadIdx.x;
    const int myl = tid & 63;
    const int og = tid >> 6;           // 0..3
    const int l = l0 + myl;

    // zero the atomic accumulation target + counters (scan runs after prep)
    if (tid < 32) g_yb[blockIdx.x * 32 + tid] = 0.0f;
    if (blockIdx.x == 0 && tid < B0) g_cnt[tid] = 0u;

    __shared__ float sWdt[1024];       // xc_w rows 0..31 ([r][d])
    __shared__ float sWbc[1024];       // xc_w rows 32..63 (B then C)
    __shared__ float sDt[1024];        // dtc_w[k] ([d][r])
    __shared__ float sM[1024];         // fused dtc_w @ xc_w[:RK]
    __shared__ float sU[64 * 33];      // padded u[l][d]
    __shared__ float sBC[64 * 17];     // padded B[l][n]
    __shared__ float sCC[64 * 17];     // padded C[l][n]
    __shared__ float sCin0[32], sCin1[32], sScale[32], sShift[32], sBias[32];

    for (int i = tid; i < 1024; i += 256) sWdt[i] = xc_w[k * 2048 + i];
    for (int i = tid; i < 1024; i += 256) sWbc[i] = xc_w[k * 2048 + 1024 + i];
    for (int i = tid; i < 1024; i += 256) sDt[i] = dtc_w[k * 1024 + i];
    if (tid < 32) {
        int d = tid;
        sCin0[d] = w_cin[d * 2 + 0];
        sCin1[d] = w_cin[d * 2 + 1];
        float sc = rsqrtf(bn_v[d] + 1e-5f) * bn_g[d];
        sScale[d] = sc;
        sShift[d] = bn_b[d] - bn_m[d] * sc;
        sBias[d] = dtc_b[k * 32 + d];
    }
    __syncthreads();

    // weight fusion
    for (int e = tid; e < 1024; e += 256) {
        const int d = e >> 5, dd = e & 31;
        float a = 0.0f;
#pragma unroll
        for (int r = 0; r < 32; r++) a += sDt[d * 32 + r] * sWdt[r * 32 + dd];
        sM[e] = a;
    }

    // phase 1: u for 8 d's at this thread's l
    {
        const int c = (k == 0) ? l : (511 - l);
        const float av = g_avg[b * 512 + c];
        const float mv = g_mx[b * 512 + c];
#pragma unroll
        for (int i = 0; i < 8; i++) {
            const int d = og * 8 + i;
            float v = sCin0[d] * av + sCin1[d] * mv;
            v = v * sScale[d] + sShift[d];
            v = gelu_exact(v);
            sU[myl * 33 + d] = v;
            g_U[(bk * 32 + d) * LL + l] = v;
        }
    }
    __syncthreads();

    // phase 2: per-thread u in registers, outputs split by og
    float u[32];
#pragma unroll
    for (int d = 0; d < 32; d++) u[d] = sU[myl * 33 + d];

    if (og < 2) {
#pragma unroll
        for (int i = 0; i < 16; i++) {
            const int d = og * 16 + i;
            float a = sBias[d];
#pragma unroll
            for (int dd = 0; dd < 32; dd++) a += u[dd] * sM[d * 32 + dd];
            g_Delta[(bk * 32 + d) * LL + l] = softplus_fast(a);
        }
    } else if (og == 2) {
#pragma unroll
        for (int n = 0; n < 16; n++) {
            float a = 0.0f;
#pragma unroll
            for (int d = 0; d < 32; d++) a += u[d] * sWbc[n * 32 + d];
            sBC[myl * 17 + n] = a;
        }
    } else {
#pragma unroll
        for (int n = 0; n < 16; n++) {
            float a = 0.0f;
#pragma unroll
            for (int d = 0; d < 32; d++) a += u[d] * sWbc[(16 + n) * 32 + d];
            sCC[myl * 17 + n] = a;
        }
    }
    __syncthreads();

    const size_t base = ((size_t)bk * 512 + l0) * NS;
    for (int i = tid; i < 1024; i += 256) {
        const int li = i >> 4, ni = i & 15;
        g_Bs[base + i] = sBC[li * 17 + ni];
        g_Cs[base + i] = sCC[li * 17 + ni];
    }
}

// ============================================================
// K3: scan v6 — Kogge-Stone warp carry + fused d-reduction +
//     last-block-per-b LayerNorm epilogue.
// ============================================================
__global__ void __launch_bounds__(256, 2)
scan_kernel(const float* __restrict__ Ac_logs,
            const float* __restrict__ Dcs,
            const float* __restrict__ w_cout,
            const float* __restrict__ ln_g,
            const float* __restrict__ ln_b) {
    const int tid = threadIdx.x;
    const int lane = tid & 31;
    const int half = lane >> 4;
    const int n = lane & 15;
    const int seg = (tid >> 5) * 2 + half;   // 0..15
    const int g = blockIdx.x;                // 0..2047
    const int kd = g & 63;
    const int k = kd >> 5;
    const int d = kd & 31;
    const int b = g >> 6;
    const int bkn = g >> 5;
    const int l0 = seg * 32;

    const float* __restrict__ dp = g_Delta + (size_t)g * LL + l0;
    const float* __restrict__ up = g_U + (size_t)g * LL + l0;
    const float* __restrict__ Bp = g_Bs + (size_t)bkn * (LL * NS) + (size_t)l0 * NS + n;
    const float* __restrict__ Cp = g_Cs + (size_t)bkn * (LL * NS) + (size_t)l0 * NS + n;

    const float A = -__expf(Ac_logs[kd * NS + n]);
    const float cA = A * 1.4426950408889634f;
    const float Dv = Dcs[kd];
    const float wd = w_cout[d];

    __shared__ float sA[16 * 16], sB[16 * 16], sH[16 * 16];

    float dA[32], dBu[32];

    // ---------- pass 1: load once, transform once, local (P, h_end) ----------
    {
        float h = 0.0f, P = 1.0f;
#pragma unroll
        for (int c = 0; c < 4; c++) {
            float dl[8], ul[8], bv[8];
            const float4* dp4 = (const float4*)(dp + c * 8);
            const float4* up4 = (const float4*)(up + c * 8);
#pragma unroll
            for (int q = 0; q < 2; q++) {
                float4 t = dp4[q];
                dl[q * 4] = t.x; dl[q * 4 + 1] = t.y; dl[q * 4 + 2] = t.z; dl[q * 4 + 3] = t.w;
                float4 s = up4[q];
                ul[q * 4] = s.x; ul[q * 4 + 1] = s.y; ul[q * 4 + 2] = s.z; ul[q * 4 + 3] = s.w;
            }
            const float* bc = Bp + (size_t)c * 8 * NS;
#pragma unroll
            for (int j = 0; j < 8; j++) bv[j] = bc[j * 16];  // coalesced across n
#pragma unroll
            for (int j = 0; j < 8; j++) {
                const int jj = c * 8 + j;
                dBu[jj] = dl[j] * ul[j] * bv[j];
                dA[jj] = ex2_fast(dl[j] * cA);
            }
#pragma unroll
            for (int j = 0; j < 8; j++) {
                const int jj = c * 8 + j;
                h = fmaf(dA[jj], h, dBu[jj]);
                P *= dA[jj];
            }
        }
        sA[seg * 16 + n] = P;
        sB[seg * 16 + n] = h;
    }
    __syncthreads();

    // ---------- carry: warp-level Kogge-Stone over 16 segments ----------
    // warp w handles n = {2w, 2w+1}: lanes 0-15 -> n=2w, 16-31 -> n=2w+1.
    {
        const int cw = tid >> 5;
        const int cl = tid & 31;
        const int cn = 2 * cw + (cl >> 4);
        const int cs = cl & 15;
        float Av = sA[cs * 16 + cn];
        float Bv = sB[cs * 16 + cn];
#pragma unroll
        for (int off = 1; off < 16; off <<= 1) {
            float ap = __shfl_up_sync(0xffffffffu, Av, off, 16);
            float bp = __shfl_up_sync(0xffffffffu, Bv, off, 16);
            if (cs >= off) { Bv = fmaf(Av, bp, Bv); Av *= ap; }
        }
        float hin = __shfl_up_sync(0xffffffffu, Bv, 1, 16);
        sH[cs * 16 + cn] = (cs == 0) ? 0.0f : hin;
    }
    __syncthreads();

    // ---------- pass 2: chain from exact h_in; atomic d-reduction ----------
    float h = sH[seg * 16 + n];
    const bool b3 = (n & 8) != 0;
    const bool b2 = (n & 4) != 0;
    const bool b1 = (n & 2) != 0;
    const bool b0 = (n & 1) != 0;

#pragma unroll
    for (int c = 0; c < 2; c++) {
        float cv[16];
        const float* cc = Cp + (size_t)c * 16 * NS;
#pragma unroll
        for (int j = 0; j < 16; j++) cv[j] = cc[j * 16];  // coalesced across n
        const float uk = up[c * 16 + n];
#pragma unroll
        for (int j = 0; j < 16; j++) {
            const int jj = c * 16 + j;
            h = fmaf(dA[jj], h, dBu[jj]);
            cv[j] = h * cv[j];
        }
        // folded butterfly: lane n ends with sum over states at l = l0+c*16+n
#pragma unroll
        for (int i = 0; i < 8; i++) {
            float mine = b3 ? cv[i + 8] : cv[i];
            float oth  = b3 ? cv[i]     : cv[i + 8];
            cv[i] = mine + __shfl_xor_sync(0xffffffffu, oth, 8);
        }
#pragma unroll
        for (int i = 0; i < 4; i++) {
            float mine = b2 ? cv[i + 4] : cv[i];
            float oth  = b2 ? cv[i]     : cv[i + 4];
            cv[i] = mine + __shfl_xor_sync(0xffffffffu, oth, 4);
        }
#pragma unroll
        for (int i = 0; i < 2; i++) {
            float mine = b1 ? cv[i + 2] : cv[i];
            float oth  = b1 ? cv[i]     : cv[i + 2];
            cv[i] = mine + __shfl_xor_sync(0xffffffffu, oth, 2);
        }
        {
            float mine = b0 ? cv[1] : cv[0];
            float oth  = b0 ? cv[0] : cv[1];
            cv[0] = mine + __shfl_xor_sync(0xffffffffu, oth, 1);
        }
        const float yv = cv[0] + Dv * uk;
        const int l = l0 + c * 16 + n;
        const int lmap = (k == 0) ? l : (511 - l);
        atomicAdd(&g_yb[b * 512 + lmap], wd * yv);
    }

    // ---------- epilogue: last of the 64 blocks for this b does LN ----------
    __shared__ unsigned sIsLast;
    __threadfence();
    __syncthreads();
    if (tid == 0) sIsLast = (atomicAdd(&g_cnt[b], 1u) == 63u) ? 1u : 0u;
    __syncthreads();
    if (sIsLast) {
        const float y0 = gelu_exact(g_yb[b * 512 + tid]);
        const float y1 = gelu_exact(g_yb[b * 512 + tid + 256]);
        float s = y0 + y1, s2 = y0 * y0 + y1 * y1;
#pragma unroll
        for (int o = 16; o; o >>= 1) {
            s += __shfl_xor_sync(0xffffffffu, s, o);
            s2 += __shfl_xor_sync(0xffffffffu, s2, o);
        }
        __shared__ float rs[8], rs2[8];
        __shared__ float smu, srv;
        const int w = tid >> 5;
        if ((tid & 31) == 0) { rs[w] = s; rs2[w] = s2; }
        __syncthreads();
        if (tid == 0) {
            float S = 0.0f, S2 = 0.0f;
#pragma unroll
            for (int i = 0; i < 8; i++) { S += rs[i]; S2 += rs2[i]; }
            float mu = S * (1.0f / 512.0f);
            float var = S2 * (1.0f / 512.0f) - mu * mu;
            smu = mu;
            srv = rsqrtf(var + 1e-5f);
        }
        __syncthreads();
        g_attn[b * 512 + tid] = (y0 - smu) * srv * ln_g[tid] + ln_b[tid];
        g_attn[b * 512 + tid + 256] = (y1 - smu) * srv * ln_g[tid + 256] + ln_b[tid + 256];
    }
}

// ============================================================
// K5: out = x * (1 + attn[b,c]).  512 MB traffic, HBM-bound.
// ============================================================
__global__ void out_kernel(const float* __restrict__ x, float* __restrict__ out) {
    const size_t i = (size_t)blockIdx.x * blockDim.x + threadIdx.x;
    const int bc = (int)(i >> 10);
    const float a = 1.0f + g_attn[bc];
    float4 v = ((const float4*)x)[i];
    v.x *= a; v.y *= a; v.z *= a; v.w *= a;
    ((float4*)out)[i] = v;
}

extern "C" void kernel_launch(void* const* d_in, const int* in_sizes, int n_in,
                              void* d_out, int out_size) {
    const float* x      = (const float*)d_in[0];
    const float* xc_w   = (const float*)d_in[1];
    const float* dtc_w  = (const float*)d_in[2];
    const float* dtc_b  = (const float*)d_in[3];
    const float* Ac     = (const float*)d_in[4];
    const float* Dcs    = (const float*)d_in[5];
    const float* w_cin  = (const float*)d_in[6];
    const float* bn_g   = (const float*)d_in[7];
    const float* bn_b   = (const float*)d_in[8];
    const float* bn_m   = (const float*)d_in[9];
    const float* bn_v   = (const float*)d_in[10];
    const float* w_cout = (const float*)d_in[11];
    const float* ln_g   = (const float*)d_in[12];
    const float* ln_b   = (const float*)d_in[13];

    pool_kernel<<<B0 * C0, 256>>>(x);
    prep_kernel<<<B0 * 2 * 8, 256>>>(xc_w, dtc_w, dtc_b, w_cin, bn_g, bn_b, bn_m, bn_v);
    scan_kernel<<<2048, 256>>>(Ac, Dcs, w_cout, ln_g, ln_b);
    out_kernel<<<65536, 256>>>(x, (float*)d_out);
}

// round 13
// speedup vs baseline: 1.0506x; 1.0506x over previous
#include <cuda_runtime.h>
#include <math.h>

#define B0 32
#define C0 512
#define HW 4096
#define DC 32
#define NS 16
#define RK 32
#define LL 512

// ---- global scratch (static device arrays; no runtime malloc) ----
__device__ float g_avg[B0 * C0];
__device__ float g_mx[B0 * C0];
__device__ float g_U[B0 * 2 * DC * LL];      // u layout [bk*32+d][l]
__device__ float g_Delta[B0 * 2 * DC * LL];  // post-softplus delta
__device__ float g_Bs[B0 * 2 * LL * NS];     // [bk][l][n]
__device__ float g_Cs[B0 * 2 * LL * NS];     // [bk][l][n]
__device__ float g_yb[B0 * LL];              // atomically accumulated sum_d w*y
__device__ float g_attn[B0 * C0];

__device__ __forceinline__ float gelu_exact(float v) {
    return 0.5f * v * (1.0f + erff(v * 0.70710678118654752f));
}
__device__ __forceinline__ float ex2_fast(float x) {
    float y;
    asm("ex2.approx.ftz.f32 %0, %1;" : "=f"(y) : "f"(x));
    return y;
}
__device__ __forceinline__ float softplus_fast(float a) {
    return fmaxf(a, 0.0f) + __logf(1.0f + __expf(-fabsf(a)));
}

// ============================================================
// K1: avg + max pool.  256 MB read, HBM-bound (~6.7 TB/s measured).
// ============================================================
__global__ void pool_kernel(const float* __restrict__ x) {
    int bc = blockIdx.x;
    const float4* xp = (const float4*)(x + (size_t)bc * HW);
    float s = 0.0f, m = -INFINITY;
#pragma unroll
    for (int it = 0; it < 4; it++) {
        int i = it * 256 + threadIdx.x;
        float4 v = xp[i];
        s += (v.x + v.y) + (v.z + v.w);
        m = fmaxf(m, fmaxf(fmaxf(v.x, v.y), fmaxf(v.z, v.w)));
    }
#pragma unroll
    for (int o = 16; o; o >>= 1) {
        s += __shfl_xor_sync(0xffffffffu, s, o);
        m = fmaxf(m, __shfl_xor_sync(0xffffffffu, m, o));
    }
    __shared__ float ss[8], sm[8];
    int w = threadIdx.x >> 5;
    if ((threadIdx.x & 31) == 0) { ss[w] = s; sm[w] = m; }
    __syncthreads();
    if (threadIdx.x == 0) {
        float S = ss[0], M = sm[0];
#pragma unroll
        for (int i = 1; i < 8; i++) { S += ss[i]; M = fmaxf(M, sm[i]); }
        g_avg[bc] = S * (1.0f / (float)HW);
        g_mx[bc] = M;
    }
}

// ============================================================
// K2: prep v2 (512 blocks x 256 thr); zeroes g_yb.
// ============================================================
__global__ void __launch_bounds__(256)
prep_kernel(const float* __restrict__ xc_w,
            const float* __restrict__ dtc_w,
            const float* __restrict__ dtc_b,
            const float* __restrict__ w_cin,
            const float* __restrict__ bn_g,
            const float* __restrict__ bn_b,
            const float* __restrict__ bn_m,
            const float* __restrict__ bn_v) {
    const int bk = blockIdx.x >> 3;
    const int b = bk >> 1, k = bk & 1;
    const int l0 = (blockIdx.x & 7) << 6;
    const int tid = threadIdx.x;
    const int myl = tid & 63;
    const int og = tid >> 6;           // 0..3
    const int l = l0 + myl;

    // zero the atomic accumulation target (scan runs strictly after prep)
    if (tid < 32) g_yb[blockIdx.x * 32 + tid] = 0.0f;

    __shared__ float sWdt[1024];       // xc_w rows 0..31 ([r][d])
    __shared__ float sWbc[1024];       // xc_w rows 32..63 (B then C)
    __shared__ float sDt[1024];        // dtc_w[k] ([d][r])
    __shared__ float sM[1024];         // fused dtc_w @ xc_w[:RK]
    __shared__ float sU[64 * 33];      // padded u[l][d]
    __shared__ float sBC[64 * 17];     // padded B[l][n]
    __shared__ float sCC[64 * 17];     // padded C[l][n]
    __shared__ float sCin0[32], sCin1[32], sScale[32], sShift[32], sBias[32];

    for (int i = tid; i < 1024; i += 256) sWdt[i] = xc_w[k * 2048 + i];
    for (int i = tid; i < 1024; i += 256) sWbc[i] = xc_w[k * 2048 + 1024 + i];
    for (int i = tid; i < 1024; i += 256) sDt[i] = dtc_w[k * 1024 + i];
    if (tid < 32) {
        int d = tid;
        sCin0[d] = w_cin[d * 2 + 0];
        sCin1[d] = w_cin[d * 2 + 1];
        float sc = rsqrtf(bn_v[d] + 1e-5f) * bn_g[d];
        sScale[d] = sc;
        sShift[d] = bn_b[d] - bn_m[d] * sc;
        sBias[d] = dtc_b[k * 32 + d];
    }
    __syncthreads();

    // weight fusion
    for (int e = tid; e < 1024; e += 256) {
        const int d = e >> 5, dd = e & 31;
        float a = 0.0f;
#pragma unroll
        for (int r = 0; r < 32; r++) a += sDt[d * 32 + r] * sWdt[r * 32 + dd];
        sM[e] = a;
    }

    // phase 1: u for 8 d's at this thread's l
    {
        const int c = (k == 0) ? l : (511 - l);
        const float av = g_avg[b * 512 + c];
        const float mv = g_mx[b * 512 + c];
#pragma unroll
        for (int i = 0; i < 8; i++) {
            const int d = og * 8 + i;
            float v = sCin0[d] * av + sCin1[d] * mv;
            v = v * sScale[d] + sShift[d];
            v = gelu_exact(v);
            sU[myl * 33 + d] = v;
            g_U[(bk * 32 + d) * LL + l] = v;
        }
    }
    __syncthreads();

    // phase 2: per-thread u in registers, outputs split by og
    float u[32];
#pragma unroll
    for (int d = 0; d < 32; d++) u[d] = sU[myl * 33 + d];

    if (og < 2) {
#pragma unroll
        for (int i = 0; i < 16; i++) {
            const int d = og * 16 + i;
            float a = sBias[d];
#pragma unroll
            for (int dd = 0; dd < 32; dd++) a += u[dd] * sM[d * 32 + dd];
            g_Delta[(bk * 32 + d) * LL + l] = softplus_fast(a);
        }
    } else if (og == 2) {
#pragma unroll
        for (int n = 0; n < 16; n++) {
            float a = 0.0f;
#pragma unroll
            for (int d = 0; d < 32; d++) a += u[d] * sWbc[n * 32 + d];
            sBC[myl * 17 + n] = a;
        }
    } else {
#pragma unroll
        for (int n = 0; n < 16; n++) {
            float a = 0.0f;
#pragma unroll
            for (int d = 0; d < 32; d++) a += u[d] * sWbc[(16 + n) * 32 + d];
            sCC[myl * 17 + n] = a;
        }
    }
    __syncthreads();

    const size_t base = ((size_t)bk * 512 + l0) * NS;
    for (int i = tid; i < 1024; i += 256) {
        const int li = i >> 4, ni = i & 15;
        g_Bs[base + i] = sBC[li * 17 + ni];
        g_Cs[base + i] = sCC[li * 17 + ni];
    }
}

// ============================================================
// K3: segment-parallel scan v5 (R11 measured-best) — serial carry,
//     fused atomic d-reduction into g_yb.
// ============================================================
__global__ void __launch_bounds__(256, 2)
scan_kernel(const float* __restrict__ Ac_logs,
            const float* __restrict__ Dcs,
            const float* __restrict__ w_cout) {
    const int tid = threadIdx.x;
    const int lane = tid & 31;
    const int half = lane >> 4;
    const int n = lane & 15;
    const int seg = (tid >> 5) * 2 + half;   // 0..15
    const int g = blockIdx.x;                // 0..2047
    const int kd = g & 63;
    const int k = kd >> 5;
    const int d = kd & 31;
    const int b = g >> 6;
    const int bkn = g >> 5;
    const int l0 = seg * 32;

    const float* __restrict__ dp = g_Delta + (size_t)g * LL + l0;
    const float* __restrict__ up = g_U + (size_t)g * LL + l0;
    const float* __restrict__ Bp = g_Bs + (size_t)bkn * (LL * NS) + (size_t)l0 * NS + n;
    const float* __restrict__ Cp = g_Cs + (size_t)bkn * (LL * NS) + (size_t)l0 * NS + n;

    const float A = -__expf(Ac_logs[kd * NS + n]);
    const float cA = A * 1.4426950408889634f;
    const float Dv = Dcs[kd];
    const float wd = w_cout[d];

    __shared__ float sA[16 * 16], sB[16 * 16], sH[16 * 16];

    float dA[32], dBu[32];

    // ---------- pass 1: load once, transform once, local (P, h_end) ----------
    {
        float h = 0.0f, P = 1.0f;
#pragma unroll
        for (int c = 0; c < 4; c++) {
            float dl[8], ul[8], bv[8];
            const float4* dp4 = (const float4*)(dp + c * 8);
            const float4* up4 = (const float4*)(up + c * 8);
#pragma unroll
            for (int q = 0; q < 2; q++) {
                float4 t = dp4[q];
                dl[q * 4] = t.x; dl[q * 4 + 1] = t.y; dl[q * 4 + 2] = t.z; dl[q * 4 + 3] = t.w;
                float4 s = up4[q];
                ul[q * 4] = s.x; ul[q * 4 + 1] = s.y; ul[q * 4 + 2] = s.z; ul[q * 4 + 3] = s.w;
            }
            const float* bc = Bp + (size_t)c * 8 * NS;
#pragma unroll
            for (int j = 0; j < 8; j++) bv[j] = bc[j * 16];  // coalesced across n
#pragma unroll
            for (int j = 0; j < 8; j++) {
                const int jj = c * 8 + j;
                dBu[jj] = dl[j] * ul[j] * bv[j];
                dA[jj] = ex2_fast(dl[j] * cA);
            }
#pragma unroll
            for (int j = 0; j < 8; j++) {
                const int jj = c * 8 + j;
                h = fmaf(dA[jj], h, dBu[jj]);
                P *= dA[jj];
            }
        }
        sA[seg * 16 + n] = P;
        sB[seg * 16 + n] = h;
    }
    __syncthreads();

    // ---------- carry resolution (serial over 16 segments) ----------
    if (tid < 16) {
        float hc = 0.0f;
        sH[tid] = 0.0f;
#pragma unroll
        for (int s = 1; s < 16; s++) {
            hc = fmaf(sA[(s - 1) * 16 + tid], hc, sB[(s - 1) * 16 + tid]);
            sH[s * 16 + tid] = hc;
        }
    }
    __syncthreads();

    // ---------- pass 2: chain from exact h_in; atomic d-reduction ----------
    float h = sH[seg * 16 + n];
    const bool b3 = (n & 8) != 0;
    const bool b2 = (n & 4) != 0;
    const bool b1 = (n & 2) != 0;
    const bool b0 = (n & 1) != 0;

#pragma unroll
    for (int c = 0; c < 2; c++) {
        float cv[16];
        const float* cc = Cp + (size_t)c * 16 * NS;
#pragma unroll
        for (int j = 0; j < 16; j++) cv[j] = cc[j * 16];  // coalesced across n
        const float uk = up[c * 16 + n];
#pragma unroll
        for (int j = 0; j < 16; j++) {
            const int jj = c * 16 + j;
            h = fmaf(dA[jj], h, dBu[jj]);
            cv[j] = h * cv[j];
        }
        // folded butterfly: lane n ends with sum over states at l = l0+c*16+n
#pragma unroll
        for (int i = 0; i < 8; i++) {
            float mine = b3 ? cv[i + 8] : cv[i];
            float oth  = b3 ? cv[i]     : cv[i + 8];
            cv[i] = mine + __shfl_xor_sync(0xffffffffu, oth, 8);
        }
#pragma unroll
        for (int i = 0; i < 4; i++) {
            float mine = b2 ? cv[i + 4] : cv[i];
            float oth  = b2 ? cv[i]     : cv[i + 4];
            cv[i] = mine + __shfl_xor_sync(0xffffffffu, oth, 4);
        }
#pragma unroll
        for (int i = 0; i < 2; i++) {
            float mine = b1 ? cv[i + 2] : cv[i];
            float oth  = b1 ? cv[i]     : cv[i + 2];
            cv[i] = mine + __shfl_xor_sync(0xffffffffu, oth, 2);
        }
        {
            float mine = b0 ? cv[1] : cv[0];
            float oth  = b0 ? cv[0] : cv[1];
            cv[0] = mine + __shfl_xor_sync(0xffffffffu, oth, 1);
        }
        const float yv = cv[0] + Dv * uk;
        const int l = l0 + c * 16 + n;
        const int lmap = (k == 0) ? l : (511 - l);
        atomicAdd(&g_yb[b * 512 + lmap], wd * yv);
    }
}

// ============================================================
// K4: gelu + LayerNorm over L per batch -> attn.
// ============================================================
__global__ void ln_kernel(const float* __restrict__ ln_g,
                          const float* __restrict__ ln_b) {
    const int b = blockIdx.x;
    const int l = threadIdx.x;
    const float yb = gelu_exact(g_yb[b * 512 + l]);
    float s = yb, s2 = yb * yb;
#pragma unroll
    for (int o = 16; o; o >>= 1) {
        s += __shfl_xor_sync(0xffffffffu, s, o);
        s2 += __shfl_xor_sync(0xffffffffu, s2, o);
    }
    __shared__ float rs[16], rs2[16];
    __shared__ float smu, srv;
    const int w = l >> 5;
    if ((l & 31) == 0) { rs[w] = s; rs2[w] = s2; }
    __syncthreads();
    if (l == 0) {
        float S = 0.0f, S2 = 0.0f;
#pragma unroll
        for (int i = 0; i < 16; i++) { S += rs[i]; S2 += rs2[i]; }
        float mu = S * (1.0f / 512.0f);
        float var = S2 * (1.0f / 512.0f) - mu * mu;
        smu = mu;
        srv = rsqrtf(var + 1e-5f);
    }
    __syncthreads();
    g_attn[b * 512 + l] = (yb - smu) * srv * ln_g[l] + ln_b[l];
}

// ============================================================
// K5: out v2 — one block = one (b,c) slice (16384 blocks x 256 thr).
//     attn loaded once (uniform); 4 batched float4 loads (MLP=4) +
//     4 stores, all coalesced.
// ============================================================
__global__ void out_kernel(const float* __restrict__ x, float* __restrict__ out) {
    const int bc = blockIdx.x;
    const float a = 1.0f + g_attn[bc];
    const float4* __restrict__ xp = (const float4*)x + (size_t)bc * 1024;
    float4* __restrict__ op = (float4*)out + (size_t)bc * 1024;
    float4 v[4];
#pragma unroll
    for (int j = 0; j < 4; j++) v[j] = xp[j * 256 + threadIdx.x];
#pragma unroll
    for (int j = 0; j < 4; j++) {
        v[j].x *= a; v[j].y *= a; v[j].z *= a; v[j].w *= a;
        op[j * 256 + threadIdx.x] = v[j];
    }
}

extern "C" void kernel_launch(void* const* d_in, const int* in_sizes, int n_in,
                              void* d_out, int out_size) {
    const float* x      = (const float*)d_in[0];
    const float* xc_w   = (const float*)d_in[1];
    const float* dtc_w  = (const float*)d_in[2];
    const float* dtc_b  = (const float*)d_in[3];
    const float* Ac     = (const float*)d_in[4];
    const float* Dcs    = (const float*)d_in[5];
    const float* w_cin  = (const float*)d_in[6];
    const float* bn_g   = (const float*)d_in[7];
    const float* bn_b   = (const float*)d_in[8];
    const float* bn_m   = (const float*)d_in[9];
    const float* bn_v   = (const float*)d_in[10];
    const float* w_cout = (const float*)d_in[11];
    const float* ln_g   = (const float*)d_in[12];
    const float* ln_b   = (const float*)d_in[13];

    pool_kernel<<<B0 * C0, 256>>>(x);
    prep_kernel<<<B0 * 2 * 8, 256>>>(xc_w, dtc_w, dtc_b, w_cin, bn_g, bn_b, bn_m, bn_v);
    scan_kernel<<<2048, 256>>>(Ac, Dcs, w_cout);
    ln_kernel<<<B0, 512>>>(ln_g, ln_b);
    out_kernel<<<B0 * C0, 256>>>(x, (float*)d_out);
}

// round 14
// speedup vs baseline: 1.0860x; 1.0336x over previous
#include <cuda_runtime.h>
#include <math.h>

#define B0 32
#define C0 512
#define HW 4096
#define DC 32
#define NS 16
#define RK 32
#define LL 512

// ---- global scratch (static device arrays; no runtime malloc) ----
__device__ float g_avg[B0 * C0];
__device__ float g_mx[B0 * C0];
__device__ float g_U[B0 * 2 * DC * LL];      // u layout [bk*32+d][l]
__device__ float g_Delta[B0 * 2 * DC * LL];  // post-softplus delta
__device__ float g_Bs[B0 * 2 * LL * NS];     // [bk][l][n]
__device__ float g_Cs[B0 * 2 * LL * NS];     // [bk][l][n]
__device__ float g_yb[B0 * LL];              // atomically accumulated sum_d w*y
__device__ float g_attn[B0 * C0];

__device__ __forceinline__ float gelu_exact(float v) {
    return 0.5f * v * (1.0f + erff(v * 0.70710678118654752f));
}
__device__ __forceinline__ float ex2_fast(float x) {
    float y;
    asm("ex2.approx.ftz.f32 %0, %1;" : "=f"(y) : "f"(x));
    return y;
}
__device__ __forceinline__ float softplus_fast(float a) {
    return fmaxf(a, 0.0f) + __logf(1.0f + __expf(-fabsf(a)));
}

// ============================================================
// K1: avg + max pool (also zeroes g_yb: one float per block).
// ============================================================
__global__ void pool_kernel(const float* __restrict__ x) {
    int bc = blockIdx.x;
    if (threadIdx.x == 0) g_yb[bc] = 0.0f;   // grid == B0*C0 == elems of g_yb
    const float4* xp = (const float4*)(x + (size_t)bc * HW);
    float s = 0.0f, m = -INFINITY;
#pragma unroll
    for (int it = 0; it < 4; it++) {
        int i = it * 256 + threadIdx.x;
        float4 v = xp[i];
        s += (v.x + v.y) + (v.z + v.w);
        m = fmaxf(m, fmaxf(fmaxf(v.x, v.y), fmaxf(v.z, v.w)));
    }
#pragma unroll
    for (int o = 16; o; o >>= 1) {
        s += __shfl_xor_sync(0xffffffffu, s, o);
        m = fmaxf(m, __shfl_xor_sync(0xffffffffu, m, o));
    }
    __shared__ float ss[8], sm[8];
    int w = threadIdx.x >> 5;
    if ((threadIdx.x & 31) == 0) { ss[w] = s; sm[w] = m; }
    __syncthreads();
    if (threadIdx.x == 0) {
        float S = ss[0], M = sm[0];
#pragma unroll
        for (int i = 1; i < 8; i++) { S += ss[i]; M = fmaxf(M, sm[i]); }
        g_avg[bc] = S * (1.0f / (float)HW);
        g_mx[bc] = M;
    }
}

// ============================================================
// K2: prep v3 — PDL: weight load + wfuse BEFORE grid sync; adds
//     the D·u contribution (w_cout[d]*Dcs[kd]*u) into g_yb.
// ============================================================
__global__ void __launch_bounds__(256)
prep_kernel(const float* __restrict__ xc_w,
            const float* __restrict__ dtc_w,
            const float* __restrict__ dtc_b,
            const float* __restrict__ w_cin,
            const float* __restrict__ bn_g,
            const float* __restrict__ bn_b,
            const float* __restrict__ bn_m,
            const float* __restrict__ bn_v,
            const float* __restrict__ Dcs,
            const float* __restrict__ w_cout) {
    const int bk = blockIdx.x >> 3;
    const int b = bk >> 1, k = bk & 1;
    const int l0 = (blockIdx.x & 7) << 6;
    const int tid = threadIdx.x;
    const int myl = tid & 63;
    const int og = tid >> 6;           // 0..3
    const int l = l0 + myl;

    __shared__ float sWdt[1024];       // xc_w rows 0..31 ([r][d])
    __shared__ float sWbc[1024];       // xc_w rows 32..63 (B then C)
    __shared__ float sDt[1024];        // dtc_w[k] ([d][r])
    __shared__ float sM[1024];         // fused dtc_w @ xc_w[:RK]
    __shared__ float sU[64 * 33];      // padded u[l][d]
    __shared__ float sBC[64 * 17];     // padded B[l][n]
    __shared__ float sCC[64 * 17];     // padded C[l][n]
    __shared__ float sCin0[32], sCin1[32], sScale[32], sShift[32], sBias[32], sWD[32];

    // ---- pre-sync work: everything independent of pool outputs ----
    for (int i = tid; i < 1024; i += 256) sWdt[i] = xc_w[k * 2048 + i];
    for (int i = tid; i < 1024; i += 256) sWbc[i] = xc_w[k * 2048 + 1024 + i];
    for (int i = tid; i < 1024; i += 256) sDt[i] = dtc_w[k * 1024 + i];
    if (tid < 32) {
        int d = tid;
        sCin0[d] = w_cin[d * 2 + 0];
        sCin1[d] = w_cin[d * 2 + 1];
        float sc = rsqrtf(bn_v[d] + 1e-5f) * bn_g[d];
        sScale[d] = sc;
        sShift[d] = bn_b[d] - bn_m[d] * sc;
        sBias[d] = dtc_b[k * 32 + d];
        sWD[d] = w_cout[d] * Dcs[k * 32 + d];
    }
    __syncthreads();
    for (int e = tid; e < 1024; e += 256) {
        const int d = e >> 5, dd = e & 31;
        float a = 0.0f;
#pragma unroll
        for (int r = 0; r < 32; r++) a += sDt[d * 32 + r] * sWdt[r * 32 + dd];
        sM[e] = a;
    }

    // ---- wait for pool ----
    cudaGridDependencySynchronize();

    // phase 1: u for 8 d's at this thread's l
    const int c = (k == 0) ? l : (511 - l);
    {
        const float av = g_avg[b * 512 + c];
        const float mv = g_mx[b * 512 + c];
#pragma unroll
        for (int i = 0; i < 8; i++) {
            const int d = og * 8 + i;
            float v = sCin0[d] * av + sCin1[d] * mv;
            v = v * sScale[d] + sShift[d];
            v = gelu_exact(v);
            sU[myl * 33 + d] = v;
            g_U[(bk * 32 + d) * LL + l] = v;
        }
    }
    __syncthreads();

    // phase 2: per-thread u in registers, outputs split by og
    float u[32];
#pragma unroll
    for (int d = 0; d < 32; d++) u[d] = sU[myl * 33 + d];

    if (og < 2) {
#pragma unroll
        for (int i = 0; i < 16; i++) {
            const int d = og * 16 + i;
            float a = sBias[d];
#pragma unroll
            for (int dd = 0; dd < 32; dd++) a += u[dd] * sM[d * 32 + dd];
            g_Delta[(bk * 32 + d) * LL + l] = softplus_fast(a);
        }
        if (og == 0) {
            // D·u term of y, folded out of the scan:
            float du = 0.0f;
#pragma unroll
            for (int d = 0; d < 32; d++) du += sWD[d] * u[d];
            atomicAdd(&g_yb[b * 512 + c], du);   // lmap == c
        }
    } else if (og == 2) {
#pragma unroll
        for (int n = 0; n < 16; n++) {
            float a = 0.0f;
#pragma unroll
            for (int d = 0; d < 32; d++) a += u[d] * sWbc[n * 32 + d];
            sBC[myl * 17 + n] = a;
        }
    } else {
#pragma unroll
        for (int n = 0; n < 16; n++) {
            float a = 0.0f;
#pragma unroll
            for (int d = 0; d < 32; d++) a += u[d] * sWbc[(16 + n) * 32 + d];
            sCC[myl * 17 + n] = a;
        }
    }
    __syncthreads();

    const size_t base = ((size_t)bk * 512 + l0) * NS;
    for (int i = tid; i < 1024; i += 256) {
        const int li = i >> 4, ni = i & 15;
        g_Bs[base + i] = sBC[li * 17 + ni];
        g_Cs[base + i] = sCC[li * 17 + ni];
    }
}

// ============================================================
// K3: scan v6 — hloc/Pcum form (pass 2 fully parallel), fused
//     atomic d-reduction; D·u handled in prep. PDL-synced.
// ============================================================
__global__ void __launch_bounds__(256, 2)
scan_kernel(const float* __restrict__ Ac_logs,
            const float* __restrict__ w_cout) {
    const int tid = threadIdx.x;
    const int lane = tid & 31;
    const int half = lane >> 4;
    const int n = lane & 15;
    const int seg = (tid >> 5) * 2 + half;   // 0..15
    const int g = blockIdx.x;                // 0..2047
    const int kd = g & 63;
    const int k = kd >> 5;
    const int d = kd & 31;
    const int b = g >> 6;
    const int bkn = g >> 5;
    const int l0 = seg * 32;

    // pre-sync work (inputs only)
    const float A = -__expf(Ac_logs[kd * NS + n]);
    const float cA = A * 1.4426950408889634f;
    const float wd = w_cout[d];

    cudaGridDependencySynchronize();

    const float* __restrict__ dp = g_Delta + (size_t)g * LL + l0;
    const float* __restrict__ up = g_U + (size_t)g * LL + l0;
    const float* __restrict__ Bp = g_Bs + (size_t)bkn * (LL * NS) + (size_t)l0 * NS + n;
    const float* __restrict__ Cp = g_Cs + (size_t)bkn * (LL * NS) + (size_t)l0 * NS + n;

    __shared__ float sA[16 * 16], sB[16 * 16], sH[16 * 16];

    float hloc[32], Pcum[32];

    // ---------- pass 1: h_local and cumulative products ----------
    {
        float h = 0.0f, P = 1.0f;
#pragma unroll
        for (int c = 0; c < 4; c++) {
            float dl[8], ul[8], bv[8];
            const float4* dp4 = (const float4*)(dp + c * 8);
            const float4* up4 = (const float4*)(up + c * 8);
#pragma unroll
            for (int q = 0; q < 2; q++) {
                float4 t = dp4[q];
                dl[q * 4] = t.x; dl[q * 4 + 1] = t.y; dl[q * 4 + 2] = t.z; dl[q * 4 + 3] = t.w;
                float4 s = up4[q];
                ul[q * 4] = s.x; ul[q * 4 + 1] = s.y; ul[q * 4 + 2] = s.z; ul[q * 4 + 3] = s.w;
            }
            const float* bc = Bp + (size_t)c * 8 * NS;
#pragma unroll
            for (int j = 0; j < 8; j++) bv[j] = bc[j * 16];  // coalesced across n
#pragma unroll
            for (int j = 0; j < 8; j++) {
                const int jj = c * 8 + j;
                const float dBu = dl[j] * ul[j] * bv[j];
                const float dAj = ex2_fast(dl[j] * cA);
                h = fmaf(dAj, h, dBu);
                P *= dAj;
                hloc[jj] = h;
                Pcum[jj] = P;
            }
        }
        sA[seg * 16 + n] = P;
        sB[seg * 16 + n] = h;
    }
    __syncthreads();

    // ---------- carry resolution (serial over 16 segments) ----------
    if (tid < 16) {
        float hc = 0.0f;
        sH[tid] = 0.0f;
#pragma unroll
        for (int s = 1; s < 16; s++) {
            hc = fmaf(sA[(s - 1) * 16 + tid], hc, sB[(s - 1) * 16 + tid]);
            sH[s * 16 + tid] = hc;
        }
    }
    __syncthreads();

    // ---------- pass 2: h_l = hloc_l + Pcum_l*h_in (independent) ----------
    const float h_in = sH[seg * 16 + n];
    const bool b3 = (n & 8) != 0;
    const bool b2 = (n & 4) != 0;
    const bool b1 = (n & 2) != 0;
    const bool b0 = (n & 1) != 0;

#pragma unroll
    for (int c = 0; c < 2; c++) {
        float cv[16];
        const float* cc = Cp + (size_t)c * 16 * NS;
#pragma unroll
        for (int j = 0; j < 16; j++) cv[j] = cc[j * 16];  // coalesced across n
#pragma unroll
        for (int j = 0; j < 16; j++) {
            const int jj = c * 16 + j;
            cv[j] = fmaf(Pcum[jj], h_in, hloc[jj]) * cv[j];
        }
        // folded butterfly: lane n ends with sum over states at l = l0+c*16+n
#pragma unroll
        for (int i = 0; i < 8; i++) {
            float mine = b3 ? cv[i + 8] : cv[i];
            float oth  = b3 ? cv[i]     : cv[i + 8];
            cv[i] = mine + __shfl_xor_sync(0xffffffffu, oth, 8);
        }
#pragma unroll
        for (int i = 0; i < 4; i++) {
            float mine = b2 ? cv[i + 4] : cv[i];
            float oth  = b2 ? cv[i]     : cv[i + 4];
            cv[i] = mine + __shfl_xor_sync(0xffffffffu, oth, 4);
        }
#pragma unroll
        for (int i = 0; i < 2; i++) {
            float mine = b1 ? cv[i + 2] : cv[i];
            float oth  = b1 ? cv[i]     : cv[i + 2];
            cv[i] = mine + __shfl_xor_sync(0xffffffffu, oth, 2);
        }
        {
            float mine = b0 ? cv[1] : cv[0];
            float oth  = b0 ? cv[0] : cv[1];
            cv[0] = mine + __shfl_xor_sync(0xffffffffu, oth, 1);
        }
        const int l = l0 + c * 16 + n;
        const int lmap = (k == 0) ? l : (511 - l);
        atomicAdd(&g_yb[b * 512 + lmap], wd * cv[0]);
    }
}

// ============================================================
// K4: gelu + LayerNorm over L per batch -> attn. PDL-synced.
// ============================================================
__global__ void ln_kernel(const float* __restrict__ ln_g,
                          const float* __restrict__ ln_b) {
    const int b = blockIdx.x;
    const int l = threadIdx.x;
    const float lg = ln_g[l];
    const float lb = ln_b[l];
    cudaGridDependencySynchronize();
    const float yb = gelu_exact(g_yb[b * 512 + l]);
    float s = yb, s2 = yb * yb;
#pragma unroll
    for (int o = 16; o; o >>= 1) {
        s += __shfl_xor_sync(0xffffffffu, s, o);
        s2 += __shfl_xor_sync(0xffffffffu, s2, o);
    }
    __shared__ float rs[16], rs2[16];
    __shared__ float smu, srv;
    const int w = l >> 5;
    if ((l & 31) == 0) { rs[w] = s; rs2[w] = s2; }
    __syncthreads();
    if (l == 0) {
        float S = 0.0f, S2 = 0.0f;
#pragma unroll
        for (int i = 0; i < 16; i++) { S += rs[i]; S2 += rs2[i]; }
        float mu = S * (1.0f / 512.0f);
        float var = S2 * (1.0f / 512.0f) - mu * mu;
        smu = mu;
        srv = rsqrtf(var + 1e-5f);
    }
    __syncthreads();
    g_attn[b * 512 + l] = (yb - smu) * srv * lg + lb;
}

// ============================================================
// K5: out v3 — PDL: prefetch x DURING ln, then sync, scale, store.
// ============================================================
__global__ void out_kernel(const float* __restrict__ x, float* __restrict__ out) {
    const int bc = blockIdx.x;
    const float4* __restrict__ xp = (const float4*)x + (size_t)bc * 1024;
    float4* __restrict__ op = (float4*)out + (size_t)bc * 1024;
    float4 v[4];
#pragma unroll
    for (int j = 0; j < 4; j++) v[j] = xp[j * 256 + threadIdx.x];
    cudaGridDependencySynchronize();
    const float a = 1.0f + g_attn[bc];
#pragma unroll
    for (int j = 0; j < 4; j++) {
        v[j].x *= a; v[j].y *= a; v[j].z *= a; v[j].w *= a;
        op[j * 256 + threadIdx.x] = v[j];
    }
}

// ---- host-side PDL launch helper ----
template <typename F, typename... Args>
static inline void launch_pdl(F f, dim3 grid, dim3 block, Args... args) {
    cudaLaunchConfig_t cfg = {};
    cfg.gridDim = grid;
    cfg.blockDim = block;
    cfg.dynamicSmemBytes = 0;
    cfg.stream = 0;
    cudaLaunchAttribute attr[1];
    attr[0].id = cudaLaunchAttributeProgrammaticStreamSerialization;
    attr[0].val.programmaticStreamSerializationAllowed = 1;
    cfg.attrs = attr;
    cfg.numAttrs = 1;
    cudaLaunchKernelEx(&cfg, f, args...);
}

extern "C" void kernel_launch(void* const* d_in, const int* in_sizes, int n_in,
                              void* d_out, int out_size) {
    const float* x      = (const float*)d_in[0];
    const float* xc_w   = (const float*)d_in[1];
    const float* dtc_w  = (const float*)d_in[2];
    const float* dtc_b  = (const float*)d_in[3];
    const float* Ac     = (const float*)d_in[4];
    const float* Dcs    = (const float*)d_in[5];
    const float* w_cin  = (const float*)d_in[6];
    const float* bn_g   = (const float*)d_in[7];
    const float* bn_b   = (const float*)d_in[8];
    const float* bn_m   = (const float*)d_in[9];
    const float* bn_v   = (const float*)d_in[10];
    const float* w_cout = (const float*)d_in[11];
    const float* ln_g   = (const float*)d_in[12];
    const float* ln_b   = (const float*)d_in[13];

    pool_kernel<<<B0 * C0, 256>>>(x);
    launch_pdl(prep_kernel, dim3(B0 * 2 * 8), dim3(256),
               xc_w, dtc_w, dtc_b, w_cin, bn_g, bn_b, bn_m, bn_v, Dcs, w_cout);
    launch_pdl(scan_kernel, dim3(2048), dim3(256), Ac, w_cout);
    launch_pdl(ln_kernel, dim3(B0), dim3(512), ln_g, ln_b);
    launch_pdl(out_kernel, dim3(B0 * C0), dim3(256), x, (float*)d_out);
}